// round 2
// baseline (speedup 1.0000x reference)
#include <cuda_runtime.h>

#define FULL 0xFFFFFFFFu
#define NUM_E 256
#define TOPK 8

// monotonic float -> u32 key (order-preserving for all finite floats)
__device__ __forceinline__ unsigned f2key(float f) {
    unsigned u = __float_as_uint(f);
    return u ^ ((unsigned)((int)u >> 31) | 0x80000000u);
}
__device__ __forceinline__ float key2f(unsigned kk) {
    unsigned m = (~(unsigned)((int)kk >> 31)) | 0x80000000u;
    return __uint_as_float(kk ^ m);
}

__global__ void __launch_bounds__(256)
moe_route_kernel(const float* __restrict__ logits,
                 const float* __restrict__ bias,
                 float* __restrict__ out_idx,   // indices stored AS FLOAT (output buffer dtype is f32)
                 float* __restrict__ out_w,
                 int T)
{
    const int lane = threadIdx.x & 31;
    const int tok  = (int)((blockIdx.x * blockDim.x + threadIdx.x) >> 5);
    if (tok >= T) return;

    // coalesced row load: lane l covers experts {4l..4l+3, 128+4l..128+4l+3}
    const float4* row = reinterpret_cast<const float4*>(logits) + (size_t)tok * (NUM_E / 4);
    float4 x0 = row[lane];
    float4 x1 = row[lane + 32];
    const float4* b4 = reinterpret_cast<const float4*>(bias);
    float4 bb0 = __ldg(b4 + lane);        // L1/L2 resident (1KB shared by all tokens)
    float4 bb1 = __ldg(b4 + lane + 32);

    float xs[8] = {x0.x, x0.y, x0.z, x0.w, x1.x, x1.y, x1.z, x1.w};
    float bs[8] = {bb0.x, bb0.y, bb0.z, bb0.w, bb1.x, bb1.y, bb1.z, bb1.w};

    // sigmoid + bias -> sortable key; payload = local slot j
    unsigned k[8];
    unsigned pj[8];
#pragma unroll
    for (int j = 0; j < 8; j++) {
        float e = __expf(-xs[j]);
        float s = __fdividef(1.0f, 1.0f + e);
        k[j]  = f2key(s + bs[j]);
        pj[j] = (unsigned)j;
    }

    // Batcher odd-even mergesort, 8 elements, DESCENDING (k[0] = largest), 19 CEs
#define CE(a, b) do {                                     \
        unsigned ka = k[a], kb = k[b];                    \
        bool p = kb > ka;                                 \
        k[a] = p ? kb : ka;  k[b] = p ? ka : kb;          \
        unsigned pa = pj[a], pb = pj[b];                  \
        pj[a] = p ? pb : pa; pj[b] = p ? pa : pb;         \
    } while (0)

    CE(0,1); CE(2,3); CE(4,5); CE(6,7);
    CE(0,2); CE(1,3); CE(1,2);
    CE(4,6); CE(5,7); CE(5,6);
    CE(0,4); CE(1,5); CE(2,6); CE(3,7);
    CE(2,4); CE(3,5);
    CE(1,2); CE(3,4); CE(5,6);
#undef CE

    // pack sorted payloads as nibbles: head payload = pjpack & 7
    unsigned pjpack = 0;
#pragma unroll
    for (int j = 0; j < 8; j++) pjpack |= pj[j] << (4 * j);

    unsigned keepk = 0;  // round-lane's winning key
    int      keepg = 0;  // round-lane's winning expert index

    // 8 extraction rounds: warp max of per-lane heads via REDUX.UMAX
#pragma unroll
    for (int r = 0; r < TOPK; r++) {
        unsigned wb  = __reduce_max_sync(FULL, k[0]);
        unsigned msk = __ballot_sync(FULL, k[0] == wb);
        int src = __ffs(msk) - 1;

        int p0 = (int)(pjpack & 7u);
        int g  = 4 * lane + p0 + ((p0 & 4) ? 124 : 0);  // slot -> global expert idx
        g = __shfl_sync(FULL, g, src);

        if (lane == r) { keepk = wb; keepg = g; }

        bool q = (lane == src);   // owner consumes its head: shift down
        k[0] = q ? k[1] : k[0];
        k[1] = q ? k[2] : k[1];
        k[2] = q ? k[3] : k[2];
        k[3] = q ? k[4] : k[3];
        k[4] = q ? k[5] : k[4];
        k[5] = q ? k[6] : k[5];
        k[6] = q ? k[7] : k[6];
        pjpack = q ? (pjpack >> 4) : pjpack;
    }

    // epilogue across lanes 0..7: weight = (s+b) - b, normalize, coalesced store
    float sb = key2f(keepk);
    float w  = sb - __ldg(bias + keepg);
    float sum = w;
#pragma unroll
    for (int off = 4; off; off >>= 1)
        sum += __shfl_xor_sync(FULL, sum, off);   // oct-local reduction (lanes 0-7)
    float wn = w * __fdividef(1.0f, sum + 1e-20f);

    if (lane < TOPK) {
        out_idx[(size_t)tok * TOPK + lane] = (float)keepg;  // index as float32 value
        out_w [(size_t)tok * TOPK + lane] = wn;
    }
}

extern "C" void kernel_launch(void* const* d_in, const int* in_sizes, int n_in,
                              void* d_out, int out_size)
{
    const float* logits = (const float*)d_in[0];
    const float* bias   = (const float*)d_in[1];
    int T = in_sizes[0] / NUM_E;

    // output buffer is float32 throughout: [T*8 indices-as-float][T*8 weights]
    float* out_idx = (float*)d_out;
    float* out_w   = (float*)d_out + (size_t)T * TOPK;

    const int threads = 256;               // 8 warps = 8 tokens per block
    const int blocks  = (T + (threads / 32) - 1) / (threads / 32);
    moe_route_kernel<<<blocks, threads>>>(logits, bias, out_idx, out_w, T);
}

// round 3
// speedup vs baseline: 1.0075x; 1.0075x over previous
#include <cuda_runtime.h>

#define FULL 0xFFFFFFFFu
#define NUM_E 256
#define TOPK 8

// monotonic float -> u32 key (order-preserving for all finite floats)
__device__ __forceinline__ unsigned f2key(float f) {
    unsigned u = __float_as_uint(f);
    return u ^ ((unsigned)((int)u >> 31) | 0x80000000u);
}
__device__ __forceinline__ float key2f(unsigned kk) {
    unsigned m = (~(unsigned)((int)kk >> 31)) | 0x80000000u;
    return __uint_as_float(kk ^ m);
}

__global__ void __launch_bounds__(256)
moe_route_kernel(const float* __restrict__ logits,
                 const float* __restrict__ bias,
                 float* __restrict__ out_idx,   // indices stored AS FLOAT (output buffer dtype is f32)
                 float* __restrict__ out_w,
                 int T)
{
    const int lane = threadIdx.x & 31;
    const int tok  = (int)((blockIdx.x * blockDim.x + threadIdx.x) >> 5);
    if (tok >= T) return;

    // coalesced row load: lane l covers experts {4l..4l+3, 128+4l..128+4l+3}
    const float4* row = reinterpret_cast<const float4*>(logits) + (size_t)tok * (NUM_E / 4);
    float4 x0 = row[lane];
    float4 x1 = row[lane + 32];
    const float4* b4 = reinterpret_cast<const float4*>(bias);
    float4 bb0 = __ldg(b4 + lane);        // L1/L2 resident (1KB shared by all tokens)
    float4 bb1 = __ldg(b4 + lane + 32);

    float xs[8] = {x0.x, x0.y, x0.z, x0.w, x1.x, x1.y, x1.z, x1.w};
    float bs[8] = {bb0.x, bb0.y, bb0.z, bb0.w, bb1.x, bb1.y, bb1.z, bb1.w};

    // sigmoid + bias -> sortable key; payload = local slot j
    unsigned k[8];
    unsigned pj[8];
#pragma unroll
    for (int j = 0; j < 8; j++) {
        float e = __expf(-xs[j]);
        float s = __fdividef(1.0f, 1.0f + e);
        k[j]  = f2key(s + bs[j]);
        pj[j] = (unsigned)j;
    }

    // Batcher odd-even mergesort, 8 elements, DESCENDING (k[0] = largest), 19 CEs
#define CE(a, b) do {                                     \
        unsigned ka = k[a], kb = k[b];                    \
        bool p = kb > ka;                                 \
        k[a] = p ? kb : ka;  k[b] = p ? ka : kb;          \
        unsigned pa = pj[a], pb = pj[b];                  \
        pj[a] = p ? pb : pa; pj[b] = p ? pa : pb;         \
    } while (0)

    CE(0,1); CE(2,3); CE(4,5); CE(6,7);
    CE(0,2); CE(1,3); CE(1,2);
    CE(4,6); CE(5,7); CE(5,6);
    CE(0,4); CE(1,5); CE(2,6); CE(3,7);
    CE(2,4); CE(3,5);
    CE(1,2); CE(3,4); CE(5,6);
#undef CE

    // pack sorted payloads as nibbles: head payload = pjpack & 7
    unsigned pjpack = 0;
#pragma unroll
    for (int j = 0; j < 8; j++) pjpack |= pj[j] << (4 * j);

    unsigned keepk = 0;  // round-lane's winning key
    int      keepg = 0;  // round-lane's winning expert index

    // 8 extraction rounds: warp max of per-lane heads via REDUX.UMAX
#pragma unroll
    for (int r = 0; r < TOPK; r++) {
        unsigned wb  = __reduce_max_sync(FULL, k[0]);
        unsigned msk = __ballot_sync(FULL, k[0] == wb);
        int src = __ffs(msk) - 1;

        int p0 = (int)(pjpack & 7u);
        int g  = 4 * lane + p0 + ((p0 & 4) ? 124 : 0);  // slot -> global expert idx
        g = __shfl_sync(FULL, g, src);

        if (lane == r) { keepk = wb; keepg = g; }

        bool q = (lane == src);   // owner consumes its head: shift down
        k[0] = q ? k[1] : k[0];
        k[1] = q ? k[2] : k[1];
        k[2] = q ? k[3] : k[2];
        k[3] = q ? k[4] : k[3];
        k[4] = q ? k[5] : k[4];
        k[5] = q ? k[6] : k[5];
        k[6] = q ? k[7] : k[6];
        pjpack = q ? (pjpack >> 4) : pjpack;
    }

    // epilogue across lanes 0..7: weight = (s+b) - b, normalize, coalesced store
    float sb = key2f(keepk);
    float w  = sb - __ldg(bias + keepg);
    float sum = w;
#pragma unroll
    for (int off = 4; off; off >>= 1)
        sum += __shfl_xor_sync(FULL, sum, off);   // oct-local reduction (lanes 0-7)
    float wn = w * __fdividef(1.0f, sum + 1e-20f);

    if (lane < TOPK) {
        out_idx[(size_t)tok * TOPK + lane] = (float)keepg;  // index as float32 value
        out_w [(size_t)tok * TOPK + lane] = wn;
    }
}

extern "C" void kernel_launch(void* const* d_in, const int* in_sizes, int n_in,
                              void* d_out, int out_size)
{
    const float* logits = (const float*)d_in[0];
    const float* bias   = (const float*)d_in[1];
    int T = in_sizes[0] / NUM_E;

    // output buffer is float32 throughout: [T*8 indices-as-float][T*8 weights]
    float* out_idx = (float*)d_out;
    float* out_w   = (float*)d_out + (size_t)T * TOPK;

    const int threads = 256;               // 8 warps = 8 tokens per block
    const int blocks  = (T + (threads / 32) - 1) / (threads / 32);
    moe_route_kernel<<<blocks, threads>>>(logits, bias, out_idx, out_w, T);
}

// round 5
// speedup vs baseline: 1.2992x; 1.2895x over previous
#include <cuda_runtime.h>

#define FULL 0xFFFFFFFFu
#define NUM_E 256
#define TOPK 8

// monotonic float -> u32 key (order-preserving for all finite floats)
__device__ __forceinline__ unsigned f2key(float f) {
    unsigned u = __float_as_uint(f);
    return u ^ ((unsigned)((int)u >> 31) | 0x80000000u);
}

__device__ __forceinline__ float sigmoidf_fast(float x) {
    return __fdividef(1.0f, 1.0f + __expf(-x));
}

__global__ void __launch_bounds__(256)
moe_route_kernel(const float* __restrict__ logits,
                 const float* __restrict__ bias,
                 float* __restrict__ out_idx,   // indices stored as float32 values
                 float* __restrict__ out_w,
                 int T)
{
    const int lane = threadIdx.x & 31;
    const int tok  = (int)((blockIdx.x * blockDim.x + threadIdx.x) >> 5);
    if (tok >= T) return;   // tok uniform per warp -> whole warp exits together

    // coalesced row load: lane l covers experts {4l..4l+3, 128+4l..128+4l+3}
    const float4* row = reinterpret_cast<const float4*>(logits) + (size_t)tok * (NUM_E / 4);
    float4 x0 = row[lane];
    float4 x1 = row[lane + 32];
    const float4* b4 = reinterpret_cast<const float4*>(bias);
    float4 bb0 = __ldg(b4 + lane);
    float4 bb1 = __ldg(b4 + lane + 32);

    // ---- FAST PATH: 24-bit score + 8-bit (j,lane) field => unique keys ----
    const unsigned lanef = 31u - (unsigned)lane;
    unsigned k[8];
    {
        float xs[8] = {x0.x, x0.y, x0.z, x0.w, x1.x, x1.y, x1.z, x1.w};
        float bs[8] = {bb0.x, bb0.y, bb0.z, bb0.w, bb1.x, bb1.y, bb1.z, bb1.w};
#pragma unroll
        for (int j = 0; j < 8; j++) {
            float s = sigmoidf_fast(xs[j]);
            unsigned fld = ((7u - (unsigned)j) << 5) | lanef;
            k[j] = (f2key(s + bs[j]) & 0xFFFFFF00u) | fld;
        }
    }

    // top-4-of-8 partial sort, descending: 14 CE + 4 IMNMX
#define CED(a, b) { unsigned ta = k[a], tb = k[b]; k[a] = ta > tb ? ta : tb; k[b] = ta > tb ? tb : ta; }
    CED(0,1) CED(2,3) CED(0,2) CED(1,3) CED(1,2)     // sort k0..k3 desc
    CED(4,5) CED(6,7) CED(4,6) CED(5,7) CED(5,6)     // sort k4..k7 desc
#undef CED
    unsigned t0 = k[0] > k[7] ? k[0] : k[7];          // max-half of bitonic merge
    unsigned t1 = k[1] > k[6] ? k[1] : k[6];
    unsigned t2 = k[2] > k[5] ? k[2] : k[5];
    unsigned t3 = k[3] > k[4] ? k[3] : k[4];
    { unsigned a = t0, b = t2; t0 = a > b ? a : b; t2 = a > b ? b : a; }   // bitonic sort-4 desc
    { unsigned a = t1, b = t3; t1 = a > b ? a : b; t3 = a > b ? b : a; }
    { unsigned a = t0, b = t1; t0 = a > b ? a : b; t1 = a > b ? b : a; }
    { unsigned a = t2, b = t3; t2 = a > b ? a : b; t3 = a > b ? b : a; }

    // 8 extraction rounds + one extra REDUX for the 9th (verification)
    unsigned w[9];
    unsigned keep = 0;
#pragma unroll
    for (int r = 0; r < TOPK; r++) {
        unsigned wb = __reduce_max_sync(FULL, t0);
        w[r] = wb;
        if (lane == r) keep = wb;
        bool own = (t0 == wb);        // unique owner (field embedded in key)
        t0 = own ? t1 : t0;
        t1 = own ? t2 : t1;
        t2 = own ? t3 : t2;           // t3 never refilled: >4 consumes => dup => fallback
    }
    w[8] = __reduce_max_sync(FULL, t0);

    // verify: exact iff adjacent winners (incl. 9th) differ in upper 24 bits.
    // catches: cq ties in/straddling selection, duplicates, window staleness.
    unsigned mn = 0xFFFFFFFFu;
#pragma unroll
    for (int r = 0; r < 8; r++) {
        unsigned x = w[r] ^ w[r + 1];
        mn = x < mn ? x : mn;
    }
    bool ok = (mn >= 256u);           // warp-uniform (w[] are REDUX results)

    int g = 0;
    if (ok) {
        // decode (lane, j) from the kept winner key
        unsigned jj = 7u - ((keep >> 5) & 7u);
        unsigned sl = 31u - (keep & 31u);
        g = 4 * (int)sl + (int)jj + ((jj & 4u) ? 124 : 0);
    } else {
        // ---- EXACT FALLBACK (rare; proven R3 path, full-precision keys) ----
        float4 y0 = row[lane];        // L1/L2-hot reloads (keeps fast-path regs lean)
        float4 y1 = row[lane + 32];
        float4 cb0 = __ldg(b4 + lane);
        float4 cb1 = __ldg(b4 + lane + 32);
        float ys[8] = {y0.x, y0.y, y0.z, y0.w, y1.x, y1.y, y1.z, y1.w};
        float cs[8] = {cb0.x, cb0.y, cb0.z, cb0.w, cb1.x, cb1.y, cb1.z, cb1.w};

        unsigned fk[8];
        unsigned pj[8];
#pragma unroll
        for (int j = 0; j < 8; j++) {
            float s = sigmoidf_fast(ys[j]);
            fk[j] = f2key(s + cs[j]);
            pj[j] = (unsigned)j;
        }
        // Batcher odd-even mergesort, 8 elems, DESC, with payload (19 CE)
#define CEP(a, b) do {                                    \
            unsigned ka = fk[a], kb = fk[b];              \
            bool p = kb > ka;                             \
            fk[a] = p ? kb : ka;  fk[b] = p ? ka : kb;    \
            unsigned pa = pj[a], pb = pj[b];              \
            pj[a] = p ? pb : pa;  pj[b] = p ? pa : pb;    \
        } while (0)
        CEP(0,1); CEP(2,3); CEP(4,5); CEP(6,7);
        CEP(0,2); CEP(1,3); CEP(1,2);
        CEP(4,6); CEP(5,7); CEP(5,6);
        CEP(0,4); CEP(1,5); CEP(2,6); CEP(3,7);
        CEP(2,4); CEP(3,5);
        CEP(1,2); CEP(3,4); CEP(5,6);
#undef CEP
        unsigned pjpack = 0;
#pragma unroll
        for (int j = 0; j < 8; j++) pjpack |= pj[j] << (4 * j);

#pragma unroll
        for (int r = 0; r < TOPK; r++) {
            unsigned wb  = __reduce_max_sync(FULL, fk[0]);
            unsigned msk = __ballot_sync(FULL, fk[0] == wb);
            int src = __ffs(msk) - 1;

            int p0 = (int)(pjpack & 7u);
            int gg = 4 * lane + p0 + ((p0 & 4) ? 124 : 0);
            gg = __shfl_sync(FULL, gg, src);
            if (lane == r) g = gg;

            bool q = (lane == src);
            fk[0] = q ? fk[1] : fk[0];
            fk[1] = q ? fk[2] : fk[1];
            fk[2] = q ? fk[3] : fk[2];
            fk[3] = q ? fk[4] : fk[3];
            fk[4] = q ? fk[5] : fk[4];
            fk[5] = q ? fk[6] : fk[5];
            fk[6] = q ? fk[7] : fk[6];
            pjpack = q ? (pjpack >> 4) : pjpack;
        }
    }

    // epilogue on lanes 0..7: exact weight from (hot) logit reload, normalize, store
    if (lane < TOPK) {
        float x = __ldg(logits + (size_t)tok * NUM_E + g);
        float wgt = sigmoidf_fast(x);
        float sum = wgt;
#pragma unroll
        for (int off = 4; off; off >>= 1)
            sum += __shfl_xor_sync(0xFFu, sum, off);
        float wn = wgt * __fdividef(1.0f, sum + 1e-20f);

        out_idx[(size_t)tok * TOPK + lane] = (float)g;
        out_w [(size_t)tok * TOPK + lane] = wn;
    }
}

extern "C" void kernel_launch(void* const* d_in, const int* in_sizes, int n_in,
                              void* d_out, int out_size)
{
    const float* logits = (const float*)d_in[0];
    const float* bias   = (const float*)d_in[1];
    int T = in_sizes[0] / NUM_E;

    float* out_idx = (float*)d_out;
    float* out_w   = (float*)d_out + (size_t)T * TOPK;

    const int threads = 256;               // 8 warps = 8 tokens per block
    const int blocks  = (T + (threads / 32) - 1) / (threads / 32);
    moe_route_kernel<<<blocks, threads>>>(logits, bias, out_idx, out_w, T);
}

// round 6
// speedup vs baseline: 1.4271x; 1.0984x over previous
#include <cuda_runtime.h>

#define FULL 0xFFFFFFFFu
#define NUM_E 256
#define TOPK 8

// monotonic float -> u32 key (fallback path only)
__device__ __forceinline__ unsigned f2key(float f) {
    unsigned u = __float_as_uint(f);
    return u ^ ((unsigned)((int)u >> 31) | 0x80000000u);
}
__device__ __forceinline__ float sigmoidf_fast(float x) {
    return __fdividef(1.0f, 1.0f + __expf(-x));
}

__global__ void __launch_bounds__(256)
moe_route_kernel(const float* __restrict__ logits,
                 const float* __restrict__ bias,
                 float* __restrict__ out_idx,   // indices stored as float32 values
                 float* __restrict__ out_w,
                 int T)
{
    const int lane = threadIdx.x & 31;
    const int tok  = (int)((blockIdx.x * blockDim.x + threadIdx.x) >> 5);
    if (tok >= T) return;   // tok uniform per warp

    // coalesced row load: lane l covers experts {4l..4l+3, 128+4l..128+4l+3}
    const float4* row = reinterpret_cast<const float4*>(logits) + (size_t)tok * (NUM_E / 4);
    float4 x0 = row[lane];
    float4 x1 = row[lane + 32];
    const float4* b4 = reinterpret_cast<const float4*>(bias);
    float4 bb0 = __ldg(b4 + lane);
    float4 bb1 = __ldg(b4 + lane + 32);

    // ---- FAST PATH ----
    // key = raw float bits of (sigmoid+bias), low 8 bits replaced by (j<<5)|lane.
    // Compared as SIGNED int: positives ordered correctly; negatives reversed,
    // which is harmless because >=128 experts have positive bias => the top-9
    // keys are always positive. Keys are unique (fld field). Any 24-bit-prefix
    // tie among adjacent winners triggers the exact fallback below.
    int k[8];
    {
        float xs[8] = {x0.x, x0.y, x0.z, x0.w, x1.x, x1.y, x1.z, x1.w};
        float bs[8] = {bb0.x, bb0.y, bb0.z, bb0.w, bb1.x, bb1.y, bb1.z, bb1.w};
#pragma unroll
        for (int j = 0; j < 8; j++) {
            float s = sigmoidf_fast(xs[j]);
            unsigned ub  = __float_as_uint(s + bs[j]);
            unsigned fld = ((unsigned)j << 5) | (unsigned)lane;
            k[j] = (int)((ub & 0xFFFFFF00u) | fld);
        }
    }

    // top-4-of-8 partial sort, descending, signed IMNMX
#define CED(a, b) { int hi = max(k[a], k[b]); int lo = min(k[a], k[b]); k[a] = hi; k[b] = lo; }
    CED(0,1) CED(2,3) CED(0,2) CED(1,3) CED(1,2)     // sort k0..k3 desc
    CED(4,5) CED(6,7) CED(4,6) CED(5,7) CED(5,6)     // sort k4..k7 desc
#undef CED
    int t0 = max(k[0], k[7]);                         // max-half of bitonic merge
    int t1 = max(k[1], k[6]);
    int t2 = max(k[2], k[5]);
    int t3 = max(k[3], k[4]);
    { int a = t0, b = t2; t0 = max(a, b); t2 = min(a, b); }   // bitonic sort-4 desc
    { int a = t1, b = t3; t1 = max(a, b); t3 = min(a, b); }
    { int a = t0, b = t1; t0 = max(a, b); t1 = min(a, b); }
    { int a = t2, b = t3; t2 = max(a, b); t3 = min(a, b); }

    // 8 extraction rounds + 9th REDUX for verification.
    // Shift chain as float-bitcast selects (FSEL; bit-exact, may ride fma pipe).
    // t3 is never refilled: >4 consumes from one lane => adjacent stale dup => fallback.
    float f0 = __int_as_float(t0), f1 = __int_as_float(t1);
    float f2 = __int_as_float(t2), f3 = __int_as_float(t3);
    int w[9];
#pragma unroll
    for (int r = 0; r < TOPK; r++) {
        int wb = __reduce_max_sync(FULL, __float_as_int(f0));
        w[r] = wb;
        bool own = (__float_as_int(f0) == wb);   // unique owner (fld embedded)
        f0 = own ? f1 : f0;
        f1 = own ? f2 : f1;
        f2 = own ? f3 : f2;
    }
    w[8] = __reduce_max_sync(FULL, __float_as_int(f0));

    // verify: exact iff all adjacent winners (incl. 9th) differ in upper 24 bits
    unsigned mn = 0xFFFFFFFFu;
#pragma unroll
    for (int r = 0; r < 8; r++) {
        unsigned x = (unsigned)w[r] ^ (unsigned)w[r + 1];
        mn = min(mn, x);
    }
    bool ok = (mn >= 256u);           // warp-uniform

    int g = 0;
    if (ok) {
        // keep = w[lane] for lanes 0..7 via select tree (REDUX broadcast values)
        int s0 = (lane & 1) ? w[1] : w[0];
        int s1 = (lane & 1) ? w[3] : w[2];
        int s2 = (lane & 1) ? w[5] : w[4];
        int s3 = (lane & 1) ? w[7] : w[6];
        int u0 = (lane & 2) ? s1 : s0;
        int u1 = (lane & 2) ? s3 : s2;
        int keep = (lane & 4) ? u1 : u0;

        unsigned kk = (unsigned)keep;
        unsigned jj = (kk >> 5) & 7u;
        unsigned sl = kk & 31u;
        g = 4 * (int)sl + (int)jj + ((jj & 4u) ? 124 : 0);
    } else {
        // ---- EXACT FALLBACK (rare): full-precision keys, proven path ----
        float4 y0 = row[lane];        // L1/L2-hot reloads
        float4 y1 = row[lane + 32];
        float4 cb0 = __ldg(b4 + lane);
        float4 cb1 = __ldg(b4 + lane + 32);
        float ys[8] = {y0.x, y0.y, y0.z, y0.w, y1.x, y1.y, y1.z, y1.w};
        float cs[8] = {cb0.x, cb0.y, cb0.z, cb0.w, cb1.x, cb1.y, cb1.z, cb1.w};

        unsigned fk[8];
        unsigned pj[8];
#pragma unroll
        for (int j = 0; j < 8; j++) {
            float s = sigmoidf_fast(ys[j]);
            fk[j] = f2key(s + cs[j]);
            pj[j] = (unsigned)j;
        }
#define CEP(a, b) do {                                    \
            unsigned ka = fk[a], kb = fk[b];              \
            bool p = kb > ka;                             \
            fk[a] = p ? kb : ka;  fk[b] = p ? ka : kb;    \
            unsigned pa = pj[a], pb = pj[b];              \
            pj[a] = p ? pb : pa;  pj[b] = p ? pa : pb;    \
        } while (0)
        CEP(0,1); CEP(2,3); CEP(4,5); CEP(6,7);
        CEP(0,2); CEP(1,3); CEP(1,2);
        CEP(4,6); CEP(5,7); CEP(5,6);
        CEP(0,4); CEP(1,5); CEP(2,6); CEP(3,7);
        CEP(2,4); CEP(3,5);
        CEP(1,2); CEP(3,4); CEP(5,6);
#undef CEP
        unsigned pjpack = 0;
#pragma unroll
        for (int j = 0; j < 8; j++) pjpack |= pj[j] << (4 * j);

#pragma unroll
        for (int r = 0; r < TOPK; r++) {
            unsigned wb  = __reduce_max_sync(FULL, fk[0]);
            unsigned msk = __ballot_sync(FULL, fk[0] == wb);
            int src = __ffs(msk) - 1;

            int p0 = (int)(pjpack & 7u);
            int gg = 4 * lane + p0 + ((p0 & 4) ? 124 : 0);
            gg = __shfl_sync(FULL, gg, src);
            if (lane == r) g = gg;

            bool q = (lane == src);
            fk[0] = q ? fk[1] : fk[0];
            fk[1] = q ? fk[2] : fk[1];
            fk[2] = q ? fk[3] : fk[2];
            fk[3] = q ? fk[4] : fk[3];
            fk[4] = q ? fk[5] : fk[4];
            fk[5] = q ? fk[6] : fk[5];
            fk[6] = q ? fk[7] : fk[6];
            pjpack = q ? (pjpack >> 4) : pjpack;
        }
    }

    // epilogue on lanes 0..7: exact weight from (hot) logit reload, normalize, store
    if (lane < TOPK) {
        float x = __ldg(logits + (size_t)tok * NUM_E + g);
        float wgt = sigmoidf_fast(x);
        float sum = wgt;
#pragma unroll
        for (int off = 4; off; off >>= 1)
            sum += __shfl_xor_sync(0xFFu, sum, off);
        float wn = wgt * __fdividef(1.0f, sum + 1e-20f);

        out_idx[(size_t)tok * TOPK + lane] = (float)g;
        out_w [(size_t)tok * TOPK + lane] = wn;
    }
}

extern "C" void kernel_launch(void* const* d_in, const int* in_sizes, int n_in,
                              void* d_out, int out_size)
{
    const float* logits = (const float*)d_in[0];
    const float* bias   = (const float*)d_in[1];
    int T = in_sizes[0] / NUM_E;

    float* out_idx = (float*)d_out;
    float* out_w   = (float*)d_out + (size_t)T * TOPK;

    const int threads = 256;               // 8 warps = 8 tokens per block
    const int blocks  = (T + (threads / 32) - 1) / (threads / 32);
    moe_route_kernel<<<blocks, threads>>>(logits, bias, out_idx, out_w, T);
}